// round 10
// baseline (speedup 1.0000x reference)
#include <cuda_runtime.h>

// pred:  (64, 512, 512) fp32   -> d_in[0]
// label: (64, 1, 512, 512) fp32 -> d_in[1]
// out:   scalar fp32
//
// Single fused kernel. Loads are batched 4 iterations deep (8x LDG.128 issued
// back-to-back) to maximize memory-level parallelism; compute runs on the
// loaded batch registers. Last-finishing block (atomic ticket) reduces the
// 1024 partials and writes the scalar, then resets the ticket.

#define BATCHES   64
#define N_ELEM    (512 * 512)
#define N_F4      (N_ELEM / 4)         // 65536 float4 per batch
#define BPB       16                   // chunks (blocks) per batch
#define TPB       256
#define NBLK      (BATCHES * BPB)      // 1024
#define F4_PER_SUB (N_F4 / BPB)        // 4096
#define ITERS     (F4_PER_SUB / TPB)   // 16
#define BATCH     4                    // load-batch depth

__device__ double g_mse [NBLK];
__device__ float  g_pval[NBLK];
__device__ int    g_pidx[NBLK];
__device__ float  g_lval[NBLK];
__device__ int    g_lidx[NBLK];
__device__ int    g_ticket = 0;

__global__ void __launch_bounds__(TPB) fused(const float4* __restrict__ pred,
                                             const float4* __restrict__ label,
                                             float* __restrict__ out)
{
    const int blk = blockIdx.x;        // 0..1023
    const int b   = blk >> 4;          // batch
    const int sub = blk & 15;          // chunk within batch (ascending index ranges)
    const int t   = threadIdx.x;

    // Running float4 offset for this thread; advances by TPB each iteration.
    size_t off = (size_t)b * N_F4 + sub * F4_PER_SUB + t;

    float pv = -3.402823466e38f; int pi = 0;
    float lv = -3.402823466e38f; int li = 0;
    float m0 = 0.0f, m1 = 0.0f, m2 = 0.0f, m3 = 0.0f;

    #pragma unroll
    for (int k = 0; k < ITERS; k += BATCH) {
        float4 P[BATCH], L[BATCH];
        // Front-batched loads: 8 independent LDG.128 in flight
        #pragma unroll
        for (int j = 0; j < BATCH; j++) P[j] = pred [off + (size_t)j * TPB];
        #pragma unroll
        for (int j = 0; j < BATCH; j++) L[j] = label[off + (size_t)j * TPB];

        #pragma unroll
        for (int j = 0; j < BATCH; j++) {
            // element index of P[j].x within this image
            const int e = (sub * F4_PER_SUB + (k + j) * TPB + t) * 4;
            const float4 p = P[j];
            const float4 l = L[j];
            // strict > keeps the FIRST max (indices ascend in j then k)
            if (p.x > pv) { pv = p.x; pi = e;     }
            if (p.y > pv) { pv = p.y; pi = e + 1; }
            if (p.z > pv) { pv = p.z; pi = e + 2; }
            if (p.w > pv) { pv = p.w; pi = e + 3; }
            if (l.x > lv) { lv = l.x; li = e;     }
            if (l.y > lv) { lv = l.y; li = e + 1; }
            if (l.z > lv) { lv = l.z; li = e + 2; }
            if (l.w > lv) { lv = l.w; li = e + 3; }
            const float dx = p.x - l.x;
            const float dy = p.y - l.y;
            const float dz = p.z - l.z;
            const float dw = p.w - l.w;
            // 4 independent accumulators shorten the FFMA chain
            m0 += dx * dx;
            m1 += dy * dy;
            m2 += dz * dz;
            m3 += dw * dw;
        }
        off += (size_t)BATCH * TPB;
    }
    const float mse = (m0 + m1) + (m2 + m3);

    __shared__ float  sPv[TPB]; __shared__ int sPi[TPB];
    __shared__ float  sLv[TPB]; __shared__ int sLi[TPB];
    __shared__ double sM [TPB];
    sPv[t] = pv; sPi[t] = pi;
    sLv[t] = lv; sLi[t] = li;
    sM[t]  = (double)mse;
    __syncthreads();

    for (int s = TPB / 2; s > 0; s >>= 1) {
        if (t < s) {
            if (sPv[t+s] > sPv[t] || (sPv[t+s] == sPv[t] && sPi[t+s] < sPi[t])) {
                sPv[t] = sPv[t+s]; sPi[t] = sPi[t+s];
            }
            if (sLv[t+s] > sLv[t] || (sLv[t+s] == sLv[t] && sLi[t+s] < sLi[t])) {
                sLv[t] = sLv[t+s]; sLi[t] = sLi[t+s];
            }
            sM[t] += sM[t+s];
        }
        __syncthreads();
    }

    __shared__ bool isLast;
    if (t == 0) {
        g_mse [blk] = sM[0];
        g_pval[blk] = sPv[0]; g_pidx[blk] = sPi[0];
        g_lval[blk] = sLv[0]; g_lidx[blk] = sLi[0];
        __threadfence();
        const int ticket = atomicAdd(&g_ticket, 1);
        isLast = (ticket == NBLK - 1);
    }
    __syncthreads();
    if (!isLast) return;

    // ---- final reduction in the last-finishing block ----
    __shared__ double fM[TPB];
    __shared__ double fIdx[BATCHES];

    {
        double s0 = 0.0;
        #pragma unroll
        for (int j = 0; j < 4; j++) s0 += g_mse[t * 4 + j];
        fM[t] = s0;
    }

    if (t < BATCHES) {
        float ppv = -3.402823466e38f; int ppi = 0;
        float llv = -3.402823466e38f; int lli = 0;
        #pragma unroll
        for (int p = 0; p < BPB; p++) {
            const int j = t * BPB + p;   // chunks in ascending index order
            float v = g_pval[j]; int i = g_pidx[j];
            if (v > ppv || (v == ppv && i < ppi)) { ppv = v; ppi = i; }
            v = g_lval[j]; i = g_lidx[j];
            if (v > llv || (v == llv && i < lli)) { llv = v; lli = i; }
        }
        const float rp = (float)(ppi >> 9), cp = (float)(ppi & 511);
        const float rl = (float)(lli >> 9), cl = (float)(lli & 511);
        const float dr = rp - rl, dc = cp - cl;
        fIdx[t] = (double)(dr * dr) + (double)(dc * dc);
    }
    __syncthreads();

    for (int s = TPB / 2; s > 0; s >>= 1) {
        if (t < s) fM[t] += fM[t + s];
        __syncthreads();
    }
    for (int s = BATCHES / 2; s > 0; s >>= 1) {
        if (t < s) fIdx[t] += fIdx[t + s];
        __syncthreads();
    }

    if (t == 0) {
        g_ticket = 0;   // reset BEFORE the output store; next replay sees 0
        __threadfence();
        const double mseT = fM[0];
        const double il   = fIdx[0];
        const double alpha = (il != 0.0) ? (mseT / il) : 1.0;
        const double loss  = (mseT + 0.25 * alpha * il) / (double)BATCHES;
        out[0] = (float)loss;
    }
}

extern "C" void kernel_launch(void* const* d_in, const int* in_sizes, int n_in,
                              void* d_out, int out_size)
{
    (void)in_sizes; (void)n_in; (void)out_size;
    const float4* pred  = (const float4*)d_in[0];
    const float4* label = (const float4*)d_in[1];
    float* out = (float*)d_out;

    fused<<<NBLK, TPB>>>(pred, label, out);
}